// round 1
// baseline (speedup 1.0000x reference)
#include <cuda_runtime.h>

typedef unsigned long long u64;
typedef unsigned int u32;

#define TILE 128
#define BK 8

// ---------------- scratch buffers (device globals; no allocation) ----------------
__device__ float g_q1[1024 * 1024];      // MLP-q hidden
__device__ float g_q [1024 * 1024];      // q        [B*128, 1024]
__device__ float g_r1[4096 * 1024];      // MLP-i hidden
__device__ float g_r [4096 * 1024];      // r        [T*512, 1024]
__device__ float g_xp[4096ull * 4096];   // xproj L1 [T*512, 4096]
__device__ float g_gates[512 * 4096];
__device__ float g_h1[512 * 1024];
__device__ float g_c1[512 * 1024];
__device__ float g_h2[512 * 1024];
__device__ float g_c2[512 * 1024];

// ---------------- f32x2 helpers (FFMA2 — PTX-only on sm_103a) ----------------
__device__ __forceinline__ u64 pack2(float x) {
    u64 r; u32 a = __float_as_uint(x);
    asm("mov.b64 %0, {%1, %1};" : "=l"(r) : "r"(a));
    return r;
}
__device__ __forceinline__ void fma2(u64& d, u64 a, u64 b) {
    asm("fma.rn.f32x2 %0, %1, %2, %3;" : "=l"(d) : "l"(a), "l"(b), "l"(d));
}
__device__ __forceinline__ float2 unpack2(u64 v) {
    u32 lo, hi;
    asm("mov.b64 {%0, %1}, %2;" : "=r"(lo), "=r"(hi) : "l"(v));
    return make_float2(__uint_as_float(lo), __uint_as_float(hi));
}

// ---------------- NT GEMM: C[M,N] = act( A0@B0^T [+ A1@B1^T] + bias0 + bias1 + Cadd )
// A: [M,K] row-major, B: [N,K] row-major (K contiguous for both).
// Requires M%128==0, N%128==0, K%8==0.
template <bool RELU>
__global__ void __launch_bounds__(256) gemm_nt(
    const float* __restrict__ A0, const float* __restrict__ B0, int K0,
    const float* __restrict__ A1, const float* __restrict__ B1, int K1,
    const float* __restrict__ bias0, const float* __restrict__ bias1,
    const float* __restrict__ Cadd, float* __restrict__ C, int N)
{
    __shared__ float As[BK][TILE];
    __shared__ float Bs[BK][TILE];

    const int tid  = threadIdx.x;
    const int tx   = tid & 15;       // 16 col-threads
    const int ty   = tid >> 4;       // 16 row-threads
    const int m0   = blockIdx.y * TILE;
    const int n0   = blockIdx.x * TILE;
    const int lrow = tid >> 1;       // 0..127
    const int lk   = (tid & 1) * 4;  // 0 or 4

    u64 acc[8][4];
#pragma unroll
    for (int i = 0; i < 8; ++i)
#pragma unroll
        for (int j = 0; j < 4; ++j) acc[i][j] = 0ull;

    for (int p = 0; p < 2; ++p) {
        const float* A = p ? A1 : A0;
        const float* B = p ? B1 : B0;
        const int    K = p ? K1 : K0;
        if (A == nullptr) break;

        const float* ap = A + (size_t)(m0 + lrow) * K + lk;
        const float* bp = B + (size_t)(n0 + lrow) * K + lk;

        for (int k0 = 0; k0 < K; k0 += BK) {
            float4 av = *(const float4*)(ap + k0);
            float4 bv = *(const float4*)(bp + k0);
            __syncthreads();
            As[lk + 0][lrow] = av.x; As[lk + 1][lrow] = av.y;
            As[lk + 2][lrow] = av.z; As[lk + 3][lrow] = av.w;
            Bs[lk + 0][lrow] = bv.x; Bs[lk + 1][lrow] = bv.y;
            Bs[lk + 2][lrow] = bv.z; Bs[lk + 3][lrow] = bv.w;
            __syncthreads();
#pragma unroll
            for (int kk = 0; kk < BK; ++kk) {
                float4 a0v = *(const float4*)&As[kk][ty * 8];
                float4 a1v = *(const float4*)&As[kk][ty * 8 + 4];
                const u64* bq = (const u64*)&Bs[kk][tx * 8];
                u64 b2[4];
#pragma unroll
                for (int j = 0; j < 4; ++j) b2[j] = bq[j];
                float ar[8] = {a0v.x, a0v.y, a0v.z, a0v.w,
                               a1v.x, a1v.y, a1v.z, a1v.w};
#pragma unroll
                for (int i = 0; i < 8; ++i) {
                    u64 a2 = pack2(ar[i]);
#pragma unroll
                    for (int j = 0; j < 4; ++j) fma2(acc[i][j], a2, b2[j]);
                }
            }
        }
    }

#pragma unroll
    for (int i = 0; i < 8; ++i) {
        const int m = m0 + ty * 8 + i;
#pragma unroll
        for (int j = 0; j < 4; ++j) {
            const int n = n0 + tx * 8 + 2 * j;
            float2 v = unpack2(acc[i][j]);
            if (bias0) { v.x += bias0[n]; v.y += bias0[n + 1]; }
            if (bias1) { v.x += bias1[n]; v.y += bias1[n + 1]; }
            if (Cadd)  { const float* cp = Cadd + (size_t)m * N + n;
                         v.x += cp[0]; v.y += cp[1]; }
            if (RELU)  { v.x = fmaxf(v.x, 0.f); v.y = fmaxf(v.y, 0.f); }
            *(float2*)(C + (size_t)m * N + n) = v;
        }
    }
}

// ---------------- LSTM elementwise cell: gates [512,4096] -> h,c [512,1024] ----
__device__ __forceinline__ float sigmoidf_(float x) { return 1.f / (1.f + expf(-x)); }

__global__ void lstm_cell_k(const float* __restrict__ gates,
                            float* __restrict__ h, float* __restrict__ c)
{
    int idx = blockIdx.x * blockDim.x + threadIdx.x;   // < 512*1024
    int row = idx >> 10, col = idx & 1023;
    const float* g = gates + (size_t)row * 4096;
    float gi = g[col];
    float gf = g[col + 1024];
    float gg = g[col + 2048];
    float go = g[col + 3072];
    float cc = sigmoidf_(gf) * c[idx] + sigmoidf_(gi) * tanhf(gg);
    c[idx] = cc;
    h[idx] = sigmoidf_(go) * tanhf(cc);
}

__global__ void zero4_k(float* a, float* b, float* c, float* d)
{
    int i = blockIdx.x * blockDim.x + threadIdx.x;     // < 512*1024
    a[i] = 0.f; b[i] = 0.f; c[i] = 0.f; d[i] = 0.f;
}

// ---------------- final: out[b,q,0]=0; out[b,q,1+k] = dot(q[b,q,:], h[b,k,:]) ---
__global__ void final_k(const float* __restrict__ q, const float* __restrict__ h,
                        float* __restrict__ out)
{
    __shared__ float qs[32][33];
    __shared__ float hs[64][33];
    const int b  = blockIdx.x >> 2;        // 8 batches
    const int rt = blockIdx.x & 3;         // 4 row tiles of 32
    const int tid = threadIdx.x;
    const int r  = tid & 31;               // row within tile
    const int cg = tid >> 5;               // 8 col groups of 8

    float acc[8] = {0.f, 0.f, 0.f, 0.f, 0.f, 0.f, 0.f, 0.f};
    for (int k0 = 0; k0 < 1024; k0 += 32) {
        __syncthreads();
        for (int i = tid; i < 32 * 32; i += 256) {
            int rr = i >> 5, kk = i & 31;
            qs[rr][kk] = q[(size_t)(b * 128 + rt * 32 + rr) * 1024 + k0 + kk];
        }
        for (int i = tid; i < 64 * 32; i += 256) {
            int rr = i >> 5, kk = i & 31;
            hs[rr][kk] = h[(size_t)(b * 64 + rr) * 1024 + k0 + kk];
        }
        __syncthreads();
#pragma unroll
        for (int kk = 0; kk < 32; ++kk) {
            float qa = qs[r][kk];
#pragma unroll
            for (int j = 0; j < 8; ++j) acc[j] += qa * hs[cg * 8 + j][kk];
        }
    }
    const int row = rt * 32 + r;
    float* op = out + ((size_t)b * 128 + row) * 65;
#pragma unroll
    for (int j = 0; j < 8; ++j) op[1 + cg * 8 + j] = acc[j];
    if (cg == 0) op[0] = 0.f;
}

// ---------------- host launch sequence ----------------
extern "C" void kernel_launch(void* const* d_in, const int* in_sizes, int n_in,
                              void* d_out, int out_size)
{
    const float* x    = (const float*)d_in[0];   // [1024, 12544]
    const float* refx = (const float*)d_in[1];   // [8*512, 12544]
    const float* qW1  = (const float*)d_in[2];
    const float* qb1  = (const float*)d_in[3];
    const float* qW2  = (const float*)d_in[4];
    const float* qb2  = (const float*)d_in[5];
    const float* iW1  = (const float*)d_in[6];
    const float* ib1  = (const float*)d_in[7];
    const float* iW2  = (const float*)d_in[8];
    const float* ib2  = (const float*)d_in[9];
    const float* Wih1 = (const float*)d_in[10];
    const float* Whh1 = (const float*)d_in[11];
    const float* bih1 = (const float*)d_in[12];
    const float* bhh1 = (const float*)d_in[13];
    const float* Wih2 = (const float*)d_in[14];
    const float* Whh2 = (const float*)d_in[15];
    const float* bih2 = (const float*)d_in[16];
    const float* bhh2 = (const float*)d_in[17];
    float* out = (float*)d_out;

    float *q1, *q, *r1, *r, *xp, *gates, *h1, *c1, *h2, *c2;
    cudaGetSymbolAddress((void**)&q1,    g_q1);
    cudaGetSymbolAddress((void**)&q,     g_q);
    cudaGetSymbolAddress((void**)&r1,    g_r1);
    cudaGetSymbolAddress((void**)&r,     g_r);
    cudaGetSymbolAddress((void**)&xp,    g_xp);
    cudaGetSymbolAddress((void**)&gates, g_gates);
    cudaGetSymbolAddress((void**)&h1,    g_h1);
    cudaGetSymbolAddress((void**)&c1,    g_c1);
    cudaGetSymbolAddress((void**)&h2,    g_h2);
    cudaGetSymbolAddress((void**)&c2,    g_c2);

    // q-MLP: [1024,12544] -> relu -> [1024,1024]
    gemm_nt<true ><<<dim3(8, 8),   256>>>(x,  qW1, 12544, nullptr, nullptr, 0, qb1, nullptr, nullptr, q1, 1024);
    gemm_nt<false><<<dim3(8, 8),   256>>>(q1, qW2, 1024,  nullptr, nullptr, 0, qb2, nullptr, nullptr, q,  1024);

    // i-MLP on ref_x: [4096,12544] -> relu -> [4096,1024]
    gemm_nt<true ><<<dim3(8, 32),  256>>>(refx, iW1, 12544, nullptr, nullptr, 0, ib1, nullptr, nullptr, r1, 1024);
    gemm_nt<false><<<dim3(8, 32),  256>>>(r1,   iW2, 1024,  nullptr, nullptr, 0, ib2, nullptr, nullptr, r,  1024);

    // Precompute layer-1 input projections for all T steps:
    // xp = r @ Wih1^T + (bih1 + bhh1)   [4096, 4096]
    gemm_nt<false><<<dim3(32, 32), 256>>>(r, Wih1, 1024, nullptr, nullptr, 0, bih1, bhh1, nullptr, xp, 4096);

    // zero LSTM state
    zero4_k<<<2048, 256>>>(h1, c1, h2, c2);

    for (int t = 0; t < 8; ++t) {
        // layer 1: gates = xp[t] + h1 @ Whh1^T
        gemm_nt<false><<<dim3(32, 4), 256>>>(h1, Whh1, 1024, nullptr, nullptr, 0,
                                             nullptr, nullptr,
                                             xp + (size_t)t * 512 * 4096, gates, 4096);
        lstm_cell_k<<<2048, 256>>>(gates, h1, c1);

        // layer 2: gates = h1 @ Wih2^T + h2 @ Whh2^T + bih2 + bhh2
        gemm_nt<false><<<dim3(32, 4), 256>>>(h1, Wih2, 1024, h2, Whh2, 1024,
                                             bih2, bhh2, nullptr, gates, 4096);
        lstm_cell_k<<<2048, 256>>>(gates, h2, c2);
    }

    // out[b,q,k]: zero col + q @ h2^T per batch
    final_k<<<32, 256>>>(q, h2, out);
}

// round 2
// speedup vs baseline: 2.1877x; 2.1877x over previous
#include <cuda_runtime.h>

typedef unsigned long long u64;
typedef unsigned int u32;

#define TILE 128
#define BK 16

// ---------------- scratch buffers (device globals; no allocation) ----------------
__device__ float g_q1[1024 * 1024];      // MLP-q hidden
__device__ float g_q [1024 * 1024];      // q        [B*128, 1024]
__device__ float g_r1[4096 * 1024];      // MLP-i hidden
__device__ float g_r [4096 * 1024];      // r        [T*512, 1024]
__device__ float g_xp[4096ull * 4096];   // xproj L1 [T*512, 4096]
__device__ float g_gates[512 * 4096];
__device__ float g_h1[512 * 1024];
__device__ float g_c1[512 * 1024];
__device__ float g_h2[512 * 1024];
__device__ float g_c2[512 * 1024];

// ---------------- f32x2 helpers (FFMA2 — PTX-only on sm_103a) ----------------
__device__ __forceinline__ u64 pack2(float x) {
    u64 r; u32 a = __float_as_uint(x);
    asm("mov.b64 %0, {%1, %1};" : "=l"(r) : "r"(a));
    return r;
}
__device__ __forceinline__ void fma2(u64& d, u64 a, u64 b) {
    asm("fma.rn.f32x2 %0, %1, %2, %3;" : "=l"(d) : "l"(a), "l"(b), "l"(d));
}
__device__ __forceinline__ float2 unpack2(u64 v) {
    u32 lo, hi;
    asm("mov.b64 {%0, %1}, %2;" : "=r"(lo), "=r"(hi) : "l"(v));
    return make_float2(__uint_as_float(lo), __uint_as_float(hi));
}

// ---------------- NT GEMM: C[M,N] = act( A0@B0^T [+ A1@B1^T] + bias0 + bias1 + Cadd )
// A: [M,K] row-major, B: [N,K] row-major (K contiguous for both).
// Requires M%128==0, N%128==0, K%16==0.
// Thread register tile: rows {ty*4+i, 64+ty*4+i}, cols {tx*4+j, 64+tx*4+j}
// -> all smem fragment loads are contiguous float4 / ulonglong2 (conflict-free).
template <bool RELU>
__global__ void __launch_bounds__(256, 2) gemm_nt(
    const float* __restrict__ A0, const float* __restrict__ B0, int K0,
    const float* __restrict__ A1, const float* __restrict__ B1, int K1,
    const float* __restrict__ bias0, const float* __restrict__ bias1,
    const float* __restrict__ Cadd, float* __restrict__ C, int N)
{
    __shared__ __align__(16) float As[2][BK][TILE];
    __shared__ __align__(16) float Bs[2][BK][TILE];

    const int tid  = threadIdx.x;
    const int tx   = tid & 15;       // 16 col-threads
    const int ty   = tid >> 4;       // 16 row-threads
    const int m0   = blockIdx.y * TILE;
    const int n0   = blockIdx.x * TILE;
    const int lrow = tid >> 1;       // 0..127
    const int lk   = (tid & 1) * 8;  // 0 or 8 (covers 8 k's via 2 float4)

    u64 acc[8][4];
#pragma unroll
    for (int i = 0; i < 8; ++i)
#pragma unroll
        for (int j = 0; j < 4; ++j) acc[i][j] = 0ull;

    for (int p = 0; p < 2; ++p) {
        const float* A = p ? A1 : A0;
        const float* B = p ? B1 : B0;
        const int    K = p ? K1 : K0;
        if (A == nullptr) break;

        const float* ap = A + (size_t)(m0 + lrow) * K + lk;
        const float* bp = B + (size_t)(n0 + lrow) * K + lk;
        const int niter = K / BK;

        // prime stage 0
        float4 av0 = *(const float4*)(ap + 0);
        float4 av1 = *(const float4*)(ap + 4);
        float4 bv0 = *(const float4*)(bp + 0);
        float4 bv1 = *(const float4*)(bp + 4);
        __syncthreads();   // (re)entering p-loop: prior reads of smem done
        As[0][lk + 0][lrow] = av0.x; As[0][lk + 1][lrow] = av0.y;
        As[0][lk + 2][lrow] = av0.z; As[0][lk + 3][lrow] = av0.w;
        As[0][lk + 4][lrow] = av1.x; As[0][lk + 5][lrow] = av1.y;
        As[0][lk + 6][lrow] = av1.z; As[0][lk + 7][lrow] = av1.w;
        Bs[0][lk + 0][lrow] = bv0.x; Bs[0][lk + 1][lrow] = bv0.y;
        Bs[0][lk + 2][lrow] = bv0.z; Bs[0][lk + 3][lrow] = bv0.w;
        Bs[0][lk + 4][lrow] = bv1.x; Bs[0][lk + 5][lrow] = bv1.y;
        Bs[0][lk + 6][lrow] = bv1.z; Bs[0][lk + 7][lrow] = bv1.w;
        __syncthreads();

        int cur = 0;
        for (int it = 0; it < niter; ++it) {
            const bool more = (it + 1 < niter);
            if (more) {
                const float* a2 = ap + (size_t)(it + 1) * BK;
                const float* b2 = bp + (size_t)(it + 1) * BK;
                av0 = *(const float4*)(a2 + 0);
                av1 = *(const float4*)(a2 + 4);
                bv0 = *(const float4*)(b2 + 0);
                bv1 = *(const float4*)(b2 + 4);
            }

#pragma unroll
            for (int kk = 0; kk < BK; ++kk) {
                float4 a0v = *(const float4*)&As[cur][kk][ty * 4];
                float4 a1v = *(const float4*)&As[cur][kk][64 + ty * 4];
                ulonglong2 bq0 = *(const ulonglong2*)&Bs[cur][kk][tx * 4];
                ulonglong2 bq1 = *(const ulonglong2*)&Bs[cur][kk][64 + tx * 4];
                u64 b2r[4] = {bq0.x, bq0.y, bq1.x, bq1.y};
                float ar[8] = {a0v.x, a0v.y, a0v.z, a0v.w,
                               a1v.x, a1v.y, a1v.z, a1v.w};
#pragma unroll
                for (int i = 0; i < 8; ++i) {
                    u64 a2p = pack2(ar[i]);
#pragma unroll
                    for (int j = 0; j < 4; ++j) fma2(acc[i][j], a2p, b2r[j]);
                }
            }

            if (more) {
                const int nxt = cur ^ 1;
                __syncthreads();   // all warps done reading buffer nxt (it-1)
                As[nxt][lk + 0][lrow] = av0.x; As[nxt][lk + 1][lrow] = av0.y;
                As[nxt][lk + 2][lrow] = av0.z; As[nxt][lk + 3][lrow] = av0.w;
                As[nxt][lk + 4][lrow] = av1.x; As[nxt][lk + 5][lrow] = av1.y;
                As[nxt][lk + 6][lrow] = av1.z; As[nxt][lk + 7][lrow] = av1.w;
                Bs[nxt][lk + 0][lrow] = bv0.x; Bs[nxt][lk + 1][lrow] = bv0.y;
                Bs[nxt][lk + 2][lrow] = bv0.z; Bs[nxt][lk + 3][lrow] = bv0.w;
                Bs[nxt][lk + 4][lrow] = bv1.x; Bs[nxt][lk + 5][lrow] = bv1.y;
                Bs[nxt][lk + 6][lrow] = bv1.z; Bs[nxt][lk + 7][lrow] = bv1.w;
                __syncthreads();
                cur = nxt;
            }
        }
    }

#pragma unroll
    for (int i = 0; i < 8; ++i) {
        const int m = m0 + ((i < 4) ? (ty * 4 + i) : (64 + ty * 4 + i - 4));
#pragma unroll
        for (int j = 0; j < 4; ++j) {
            const int n = n0 + ((j < 2) ? (tx * 4 + 2 * j)
                                        : (64 + tx * 4 + 2 * (j - 2)));
            float2 v = unpack2(acc[i][j]);
            if (bias0) { v.x += bias0[n]; v.y += bias0[n + 1]; }
            if (bias1) { v.x += bias1[n]; v.y += bias1[n + 1]; }
            if (Cadd)  { const float* cp = Cadd + (size_t)m * N + n;
                         v.x += cp[0]; v.y += cp[1]; }
            if (RELU)  { v.x = fmaxf(v.x, 0.f); v.y = fmaxf(v.y, 0.f); }
            *(float2*)(C + (size_t)m * N + n) = v;
        }
    }
}

// ---------------- LSTM elementwise cell: gates [512,4096] -> h,c [512,1024] ----
__device__ __forceinline__ float sigmoidf_(float x) { return 1.f / (1.f + expf(-x)); }

__global__ void lstm_cell_k(const float* __restrict__ gates,
                            float* __restrict__ h, float* __restrict__ c)
{
    int idx = blockIdx.x * blockDim.x + threadIdx.x;   // < 512*1024
    int row = idx >> 10, col = idx & 1023;
    const float* g = gates + (size_t)row * 4096;
    float gi = g[col];
    float gf = g[col + 1024];
    float gg = g[col + 2048];
    float go = g[col + 3072];
    float cc = sigmoidf_(gf) * c[idx] + sigmoidf_(gi) * tanhf(gg);
    c[idx] = cc;
    h[idx] = sigmoidf_(go) * tanhf(cc);
}

__global__ void zero4_k(float* a, float* b, float* c, float* d)
{
    int i = blockIdx.x * blockDim.x + threadIdx.x;     // < 512*1024
    a[i] = 0.f; b[i] = 0.f; c[i] = 0.f; d[i] = 0.f;
}

// ---------------- final: out[b,q,0]=0; out[b,q,1+k] = dot(q[b,q,:], h[b,k,:]) ---
__global__ void final_k(const float* __restrict__ q, const float* __restrict__ h,
                        float* __restrict__ out)
{
    __shared__ float qs[32][33];
    __shared__ float hs[64][33];
    const int b  = blockIdx.x >> 2;        // 8 batches
    const int rt = blockIdx.x & 3;         // 4 row tiles of 32
    const int tid = threadIdx.x;
    const int r  = tid & 31;               // row within tile
    const int cg = tid >> 5;               // 8 col groups of 8

    float acc[8] = {0.f, 0.f, 0.f, 0.f, 0.f, 0.f, 0.f, 0.f};
    for (int k0 = 0; k0 < 1024; k0 += 32) {
        __syncthreads();
        for (int i = tid; i < 32 * 32; i += 256) {
            int rr = i >> 5, kk = i & 31;
            qs[rr][kk] = q[(size_t)(b * 128 + rt * 32 + rr) * 1024 + k0 + kk];
        }
        for (int i = tid; i < 64 * 32; i += 256) {
            int rr = i >> 5, kk = i & 31;
            hs[rr][kk] = h[(size_t)(b * 64 + rr) * 1024 + k0 + kk];
        }
        __syncthreads();
#pragma unroll
        for (int kk = 0; kk < 32; ++kk) {
            float qa = qs[r][kk];
#pragma unroll
            for (int j = 0; j < 8; ++j) acc[j] += qa * hs[cg * 8 + j][kk];
        }
    }
    const int row = rt * 32 + r;
    float* op = out + ((size_t)b * 128 + row) * 65;
#pragma unroll
    for (int j = 0; j < 8; ++j) op[1 + cg * 8 + j] = acc[j];
    if (cg == 0) op[0] = 0.f;
}

// ---------------- host launch sequence ----------------
extern "C" void kernel_launch(void* const* d_in, const int* in_sizes, int n_in,
                              void* d_out, int out_size)
{
    const float* x    = (const float*)d_in[0];   // [1024, 12544]
    const float* refx = (const float*)d_in[1];   // [8*512, 12544]
    const float* qW1  = (const float*)d_in[2];
    const float* qb1  = (const float*)d_in[3];
    const float* qW2  = (const float*)d_in[4];
    const float* qb2  = (const float*)d_in[5];
    const float* iW1  = (const float*)d_in[6];
    const float* ib1  = (const float*)d_in[7];
    const float* iW2  = (const float*)d_in[8];
    const float* ib2  = (const float*)d_in[9];
    const float* Wih1 = (const float*)d_in[10];
    const float* Whh1 = (const float*)d_in[11];
    const float* bih1 = (const float*)d_in[12];
    const float* bhh1 = (const float*)d_in[13];
    const float* Wih2 = (const float*)d_in[14];
    const float* Whh2 = (const float*)d_in[15];
    const float* bih2 = (const float*)d_in[16];
    const float* bhh2 = (const float*)d_in[17];
    float* out = (float*)d_out;

    float *q1, *q, *r1, *r, *xp, *gates, *h1, *c1, *h2, *c2;
    cudaGetSymbolAddress((void**)&q1,    g_q1);
    cudaGetSymbolAddress((void**)&q,     g_q);
    cudaGetSymbolAddress((void**)&r1,    g_r1);
    cudaGetSymbolAddress((void**)&r,     g_r);
    cudaGetSymbolAddress((void**)&xp,    g_xp);
    cudaGetSymbolAddress((void**)&gates, g_gates);
    cudaGetSymbolAddress((void**)&h1,    g_h1);
    cudaGetSymbolAddress((void**)&c1,    g_c1);
    cudaGetSymbolAddress((void**)&h2,    g_h2);
    cudaGetSymbolAddress((void**)&c2,    g_c2);

    // q-MLP: [1024,12544] -> relu -> [1024,1024]
    gemm_nt<true ><<<dim3(8, 8),   256>>>(x,  qW1, 12544, nullptr, nullptr, 0, qb1, nullptr, nullptr, q1, 1024);
    gemm_nt<false><<<dim3(8, 8),   256>>>(q1, qW2, 1024,  nullptr, nullptr, 0, qb2, nullptr, nullptr, q,  1024);

    // i-MLP on ref_x: [4096,12544] -> relu -> [4096,1024]
    gemm_nt<true ><<<dim3(8, 32),  256>>>(refx, iW1, 12544, nullptr, nullptr, 0, ib1, nullptr, nullptr, r1, 1024);
    gemm_nt<false><<<dim3(8, 32),  256>>>(r1,   iW2, 1024,  nullptr, nullptr, 0, ib2, nullptr, nullptr, r,  1024);

    // Precompute layer-1 input projections for all T steps:
    // xp = r @ Wih1^T + (bih1 + bhh1)   [4096, 4096]
    gemm_nt<false><<<dim3(32, 32), 256>>>(r, Wih1, 1024, nullptr, nullptr, 0, bih1, bhh1, nullptr, xp, 4096);

    // zero LSTM state
    zero4_k<<<2048, 256>>>(h1, c1, h2, c2);

    for (int t = 0; t < 8; ++t) {
        // layer 1: gates = xp[t] + h1 @ Whh1^T
        gemm_nt<false><<<dim3(32, 4), 256>>>(h1, Whh1, 1024, nullptr, nullptr, 0,
                                             nullptr, nullptr,
                                             xp + (size_t)t * 512 * 4096, gates, 4096);
        lstm_cell_k<<<2048, 256>>>(gates, h1, c1);

        // layer 2: gates = h1 @ Wih2^T + h2 @ Whh2^T + bih2 + bhh2
        gemm_nt<false><<<dim3(32, 4), 256>>>(h1, Wih2, 1024, h2, Whh2, 1024,
                                             bih2, bhh2, nullptr, gates, 4096);
        lstm_cell_k<<<2048, 256>>>(gates, h2, c2);
    }

    // out[b,q,k]: zero col + q @ h2^T per batch
    final_k<<<32, 256>>>(q, h2, out);
}

// round 4
// speedup vs baseline: 4.5413x; 2.0758x over previous
#include <cuda_runtime.h>
#include <cuda_bf16.h>

typedef unsigned long long u64;
typedef unsigned int u32;
typedef __nv_bfloat16 bf16;

// ================= scratch (device globals; no allocation) =================
__device__ bf16 g_x_h [1024u*12544], g_x_l [1024u*12544];
__device__ bf16 g_rx_h[4096u*12544], g_rx_l[4096u*12544];
__device__ bf16 g_qW1_h[1024u*12544], g_qW1_l[1024u*12544];
__device__ bf16 g_iW1_h[1024u*12544], g_iW1_l[1024u*12544];
__device__ bf16 g_qW2_h[1024u*1024], g_qW2_l[1024u*1024];
__device__ bf16 g_iW2_h[1024u*1024], g_iW2_l[1024u*1024];
__device__ bf16 g_Wih1_h[4096u*1024], g_Wih1_l[4096u*1024];
__device__ bf16 g_Whh1_h[4096u*1024], g_Whh1_l[4096u*1024];
__device__ bf16 g_Wih2_h[4096u*1024], g_Wih2_l[4096u*1024];
__device__ bf16 g_Whh2_h[4096u*1024], g_Whh2_l[4096u*1024];
__device__ bf16 g_q1_h[1024u*1024], g_q1_l[1024u*1024];
__device__ bf16 g_r1_h[4096u*1024], g_r1_l[4096u*1024];
__device__ bf16 g_r_h [4096u*1024], g_r_l [4096u*1024];
__device__ bf16 g_h1_h[512u*1024], g_h1_l[512u*1024];
__device__ bf16 g_h2_h[512u*1024], g_h2_l[512u*1024];
// fp32
__device__ float g_q  [1024u*1024];
__device__ float g_xp [4096ull*4096];
__device__ float g_gates[512u*4096];
__device__ float g_c1[512u*1024], g_c2[512u*1024], g_h2f[512u*1024];

// ================= PTX helpers (baseline sm_80+ PTX only) =================
__device__ __forceinline__ u32 smem_u32(const void* p) {
    u32 a;
    asm("{ .reg .u64 t; cvta.to.shared.u64 t, %1; cvt.u32.u64 %0, t; }" : "=r"(a) : "l"(p));
    return a;
}
#define SW128(o) ((o) ^ (((o) >> 3) & 0x70))

__device__ __forceinline__ void cp16(u32 dst, const void* src) {
    asm volatile("cp.async.cg.shared.global [%0], [%1], 16;" :: "r"(dst), "l"(src));
}
#define CP_COMMIT()  asm volatile("cp.async.commit_group;" ::: "memory")
#define CP_WAIT(n)   asm volatile("cp.async.wait_group %0;" :: "n"(n) : "memory")

__device__ __forceinline__ void ldm_x4(u32& r0, u32& r1, u32& r2, u32& r3, u32 addr) {
    asm volatile("ldmatrix.sync.aligned.m8n8.x4.shared.b16 {%0,%1,%2,%3}, [%4];"
                 : "=r"(r0), "=r"(r1), "=r"(r2), "=r"(r3) : "r"(addr));
}
__device__ __forceinline__ void mma_bf16(float* d, const u32* a, const u32* b) {
    asm volatile("mma.sync.aligned.m16n8k16.row.col.f32.bf16.bf16.f32 "
                 "{%0,%1,%2,%3}, {%4,%5,%6,%7}, {%8,%9}, {%0,%1,%2,%3};"
                 : "+f"(d[0]), "+f"(d[1]), "+f"(d[2]), "+f"(d[3])
                 : "r"(a[0]), "r"(a[1]), "r"(a[2]), "r"(a[3]), "r"(b[0]), "r"(b[1]));
}

// ================= bf16x3 tensor-core GEMM (mma.sync) =================
// C[M,N] = act( A0@B0^T [+ A1@B1^T] + bias0 + bias1 + Cadd )
// A,B as bf16 hi/lo pairs, [rows, K] row-major. M%128==0, N%128==0, K%64==0.
// CTA tile 128x128, 8 warps of 64x32, K-chunk 64, 2-stage cp.async pipeline.
template <bool RELU>
__global__ void __launch_bounds__(256, 1) gemm_mma(
    const bf16* __restrict__ A0h, const bf16* __restrict__ A0l,
    const bf16* __restrict__ B0h, const bf16* __restrict__ B0l, int K0,
    const bf16* __restrict__ A1h, const bf16* __restrict__ A1l,
    const bf16* __restrict__ B1h, const bf16* __restrict__ B1l, int K1,
    const float* __restrict__ bias0, const float* __restrict__ bias1,
    const float* __restrict__ Cadd,
    float* __restrict__ Cf, bf16* __restrict__ Chi, bf16* __restrict__ Clo,
    int N)
{
    extern __shared__ char sm[];
    const int tid = threadIdx.x, wid = tid >> 5, lane = tid & 31;
    const int m0 = blockIdx.y * 128, n0 = blockIdx.x * 128;
    const int wm = (wid >> 2) * 64, wn = (wid & 3) * 32;

    const int nch0 = K0 / 64;
    const int nch1 = A1h ? (K1 / 64) : 0;
    const int nch = nch0 + nch1;
    const u32 smu = smem_u32(sm);

    // stage layout: [Ah 16K][Al 16K][Bh 16K][Bl 16K] = 64KB; 2 stages
    auto load_stage = [&](int c, int s) {
        const bf16 *Ah, *Al, *Bh, *Bl; int K, k0;
        if (c < nch0) { Ah = A0h; Al = A0l; Bh = B0h; Bl = B0l; K = K0; k0 = c * 64; }
        else          { Ah = A1h; Al = A1l; Bh = B1h; Bl = B1l; K = K1; k0 = (c - nch0) * 64; }
        const u32 base = smu + s * 65536;
#pragma unroll
        for (int i = 0; i < 4; ++i) {
            int u = tid + i * 256;
            int row = u >> 3, cu = u & 7;
            u32 so = SW128((u32)(row * 128 + cu * 16));
            size_t ao = (size_t)(m0 + row) * K + k0 + cu * 8;
            size_t bo = (size_t)(n0 + row) * K + k0 + cu * 8;
            cp16(base + so,         Ah + ao);
            cp16(base + 16384 + so, Al + ao);
            cp16(base + 32768 + so, Bh + bo);
            cp16(base + 49152 + so, Bl + bo);
        }
        CP_COMMIT();
    };

    float acc[4][4][4];
#pragma unroll
    for (int i = 0; i < 4; ++i)
#pragma unroll
        for (int j = 0; j < 4; ++j)
#pragma unroll
            for (int k = 0; k < 4; ++k) acc[i][j][k] = 0.f;

    load_stage(0, 0);

    for (int c = 0; c < nch; ++c) {
        const int s = c & 1;
        if (c + 1 < nch) { load_stage(c + 1, s ^ 1); CP_WAIT(1); }
        else             { CP_WAIT(0); }
        __syncthreads();

        const u32 base = smu + s * 65536;
        const int lrow = lane & 15;
        const u32 klane = (u32)((lane >> 4) * 16);

#pragma unroll
        for (int ks = 0; ks < 4; ++ks) {
            const u32 koff = ks * 32 + klane;
            u32 ah[4][4], al[4][4], bh[4][2], bl[4][2];
#pragma unroll
            for (int mt = 0; mt < 4; ++mt) {
                u32 so = SW128((u32)((wm + mt * 16 + lrow) * 128) + koff);
                ldm_x4(ah[mt][0], ah[mt][1], ah[mt][2], ah[mt][3], base + so);
                ldm_x4(al[mt][0], al[mt][1], al[mt][2], al[mt][3], base + 16384 + so);
            }
#pragma unroll
            for (int bt = 0; bt < 2; ++bt) {
                u32 so = SW128((u32)((wn + bt * 16 + lrow) * 128) + koff);
                u32 r0, r1, r2, r3;
                ldm_x4(r0, r1, r2, r3, base + 32768 + so);
                bh[bt * 2][0] = r0; bh[bt * 2][1] = r2;
                bh[bt * 2 + 1][0] = r1; bh[bt * 2 + 1][1] = r3;
                ldm_x4(r0, r1, r2, r3, base + 49152 + so);
                bl[bt * 2][0] = r0; bl[bt * 2][1] = r2;
                bl[bt * 2 + 1][0] = r1; bl[bt * 2 + 1][1] = r3;
            }
#pragma unroll
            for (int mt = 0; mt < 4; ++mt)
#pragma unroll
                for (int nt = 0; nt < 4; ++nt) {
                    mma_bf16(acc[mt][nt], ah[mt], bh[nt]);   // hi*hi
                    mma_bf16(acc[mt][nt], ah[mt], bl[nt]);   // hi*lo
                    mma_bf16(acc[mt][nt], al[mt], bh[nt]);   // lo*hi
                }
        }
        __syncthreads();
    }

    // ---- epilogue ----
    const int r = lane >> 2, cp = (lane & 3) * 2;
#pragma unroll
    for (int mt = 0; mt < 4; ++mt)
#pragma unroll
        for (int nt = 0; nt < 4; ++nt)
#pragma unroll
            for (int half = 0; half < 2; ++half) {
                const int m = m0 + wm + mt * 16 + r + half * 8;
                const int n = n0 + wn + nt * 8 + cp;
                float v0 = acc[mt][nt][half * 2];
                float v1 = acc[mt][nt][half * 2 + 1];
                if (bias0) { v0 += bias0[n]; v1 += bias0[n + 1]; }
                if (bias1) { v0 += bias1[n]; v1 += bias1[n + 1]; }
                if (Cadd)  { const float* q = Cadd + (size_t)m * N + n;
                             v0 += q[0]; v1 += q[1]; }
                if (RELU)  { v0 = fmaxf(v0, 0.f); v1 = fmaxf(v1, 0.f); }
                if (Cf) *(float2*)(Cf + (size_t)m * N + n) = make_float2(v0, v1);
                if (Chi) {
                    bf16 h0 = __float2bfloat16(v0), h1 = __float2bfloat16(v1);
                    bf16 l0 = __float2bfloat16(v0 - __bfloat162float(h0));
                    bf16 l1 = __float2bfloat16(v1 - __bfloat162float(h1));
                    *(__nv_bfloat162*)(Chi + (size_t)m * N + n) = __nv_bfloat162(h0, h1);
                    *(__nv_bfloat162*)(Clo + (size_t)m * N + n) = __nv_bfloat162(l0, l1);
                }
            }
}

// ================= elementwise kernels =================
__global__ void split_k(const float* __restrict__ src, bf16* __restrict__ hi,
                        bf16* __restrict__ lo)
{
    size_t i = ((size_t)blockIdx.x * blockDim.x + threadIdx.x) * 4;
    float4 v = *(const float4*)(src + i);
    float vv[4] = {v.x, v.y, v.z, v.w};
    unsigned short hh[4], ll[4];
#pragma unroll
    for (int j = 0; j < 4; ++j) {
        bf16 h = __float2bfloat16(vv[j]);
        bf16 l = __float2bfloat16(vv[j] - __bfloat162float(h));
        hh[j] = __bfloat16_as_ushort(h);
        ll[j] = __bfloat16_as_ushort(l);
    }
    *(ushort4*)(hi + i) = make_ushort4(hh[0], hh[1], hh[2], hh[3]);
    *(ushort4*)(lo + i) = make_ushort4(ll[0], ll[1], ll[2], ll[3]);
}

__device__ __forceinline__ float sigmoidf_(float x) { return 1.f / (1.f + expf(-x)); }

__global__ void lstm_cell_k(const float* __restrict__ gates, float* __restrict__ c,
                            float* __restrict__ hf,
                            bf16* __restrict__ hh, bf16* __restrict__ hl)
{
    int idx = blockIdx.x * blockDim.x + threadIdx.x;   // < 512*1024
    int row = idx >> 10, col = idx & 1023;
    const float* g = gates + (size_t)row * 4096;
    float gi = g[col], gf = g[col + 1024], gg = g[col + 2048], go = g[col + 3072];
    float cc = sigmoidf_(gf) * c[idx] + sigmoidf_(gi) * tanhf(gg);
    c[idx] = cc;
    float h = sigmoidf_(go) * tanhf(cc);
    if (hf) hf[idx] = h;
    bf16 hb = __float2bfloat16(h);
    hh[idx] = hb;
    hl[idx] = __float2bfloat16(h - __bfloat162float(hb));
}

__global__ void zero_k(bf16* a, bf16* b, bf16* cc, bf16* d, float* e, float* f)
{
    int i = blockIdx.x * blockDim.x + threadIdx.x;     // < 512*1024
    bf16 z = __float2bfloat16(0.f);
    a[i] = z; b[i] = z; cc[i] = z; d[i] = z; e[i] = 0.f; f[i] = 0.f;
}

// ================= final einsum =================
__global__ void final_k(const float* __restrict__ q, const float* __restrict__ h,
                        float* __restrict__ out)
{
    __shared__ float qs[32][33];
    __shared__ float hs[64][33];
    const int b  = blockIdx.x >> 2;
    const int rt = blockIdx.x & 3;
    const int tid = threadIdx.x;
    const int r  = tid & 31;
    const int cg = tid >> 5;

    float acc[8] = {0.f, 0.f, 0.f, 0.f, 0.f, 0.f, 0.f, 0.f};
    for (int k0 = 0; k0 < 1024; k0 += 32) {
        __syncthreads();
        for (int i = tid; i < 32 * 32; i += 256) {
            int rr = i >> 5, kk = i & 31;
            qs[rr][kk] = q[(size_t)(b * 128 + rt * 32 + rr) * 1024 + k0 + kk];
        }
        for (int i = tid; i < 64 * 32; i += 256) {
            int rr = i >> 5, kk = i & 31;
            hs[rr][kk] = h[(size_t)(b * 64 + rr) * 1024 + k0 + kk];
        }
        __syncthreads();
#pragma unroll
        for (int kk = 0; kk < 32; ++kk) {
            float qa = qs[r][kk];
#pragma unroll
            for (int j = 0; j < 8; ++j) acc[j] += qa * hs[cg * 8 + j][kk];
        }
    }
    const int row = rt * 32 + r;
    float* op = out + ((size_t)b * 128 + row) * 65;
#pragma unroll
    for (int j = 0; j < 8; ++j) op[1 + cg * 8 + j] = acc[j];
    if (cg == 0) op[0] = 0.f;
}

// ================= host =================
static const int SMEM_GEMM = 2 * 65536;   // 128 KB

extern "C" void kernel_launch(void* const* d_in, const int* in_sizes, int n_in,
                              void* d_out, int out_size)
{
    const float* x    = (const float*)d_in[0];
    const float* refx = (const float*)d_in[1];
    const float* qW1  = (const float*)d_in[2];
    const float* qb1  = (const float*)d_in[3];
    const float* qW2  = (const float*)d_in[4];
    const float* qb2  = (const float*)d_in[5];
    const float* iW1  = (const float*)d_in[6];
    const float* ib1  = (const float*)d_in[7];
    const float* iW2  = (const float*)d_in[8];
    const float* ib2  = (const float*)d_in[9];
    const float* Wih1 = (const float*)d_in[10];
    const float* Whh1 = (const float*)d_in[11];
    const float* bih1 = (const float*)d_in[12];
    const float* bhh1 = (const float*)d_in[13];
    const float* Wih2 = (const float*)d_in[14];
    const float* Whh2 = (const float*)d_in[15];
    const float* bih2 = (const float*)d_in[16];
    const float* bhh2 = (const float*)d_in[17];
    float* out = (float*)d_out;

    cudaFuncSetAttribute(gemm_mma<true >, cudaFuncAttributeMaxDynamicSharedMemorySize, SMEM_GEMM);
    cudaFuncSetAttribute(gemm_mma<false>, cudaFuncAttributeMaxDynamicSharedMemorySize, SMEM_GEMM);

#define SYM(v, s) cudaGetSymbolAddress((void**)&v, s)
    bf16 *xh, *xl, *rxh, *rxl, *qW1h, *qW1l, *iW1h, *iW1l, *qW2h, *qW2l, *iW2h, *iW2l;
    bf16 *Wih1h, *Wih1l, *Whh1h, *Whh1l, *Wih2h, *Wih2l, *Whh2h, *Whh2l;
    bf16 *q1h, *q1l, *r1h, *r1l, *rh, *rl, *h1h, *h1l, *h2h, *h2l;
    float *q, *xp, *gates, *c1, *c2, *h2f;
    SYM(xh, g_x_h);   SYM(xl, g_x_l);   SYM(rxh, g_rx_h);   SYM(rxl, g_rx_l);
    SYM(qW1h, g_qW1_h); SYM(qW1l, g_qW1_l); SYM(iW1h, g_iW1_h); SYM(iW1l, g_iW1_l);
    SYM(qW2h, g_qW2_h); SYM(qW2l, g_qW2_l); SYM(iW2h, g_iW2_h); SYM(iW2l, g_iW2_l);
    SYM(Wih1h, g_Wih1_h); SYM(Wih1l, g_Wih1_l); SYM(Whh1h, g_Whh1_h); SYM(Whh1l, g_Whh1_l);
    SYM(Wih2h, g_Wih2_h); SYM(Wih2l, g_Wih2_l); SYM(Whh2h, g_Whh2_h); SYM(Whh2l, g_Whh2_l);
    SYM(q1h, g_q1_h); SYM(q1l, g_q1_l); SYM(r1h, g_r1_h); SYM(r1l, g_r1_l);
    SYM(rh, g_r_h);   SYM(rl, g_r_l);
    SYM(h1h, g_h1_h); SYM(h1l, g_h1_l); SYM(h2h, g_h2_h); SYM(h2l, g_h2_l);
    SYM(q, g_q); SYM(xp, g_xp); SYM(gates, g_gates);
    SYM(c1, g_c1); SYM(c2, g_c2); SYM(h2f, g_h2f);
#undef SYM

    // ---- split fp32 -> bf16 hi/lo (one-time per call) ----
#define SPL(src, h, l, n) split_k<<<(n) / 1024, 256>>>(src, h, l)
    SPL(x,    xh,   xl,   1024u * 12544);
    SPL(refx, rxh,  rxl,  4096u * 12544);
    SPL(qW1,  qW1h, qW1l, 1024u * 12544);
    SPL(iW1,  iW1h, iW1l, 1024u * 12544);
    SPL(qW2,  qW2h, qW2l, 1024u * 1024);
    SPL(iW2,  iW2h, iW2l, 1024u * 1024);
    SPL(Wih1, Wih1h, Wih1l, 4096u * 1024);
    SPL(Whh1, Whh1h, Whh1l, 4096u * 1024);
    SPL(Wih2, Wih2h, Wih2l, 4096u * 1024);
    SPL(Whh2, Whh2h, Whh2l, 4096u * 1024);
#undef SPL

#define NB8 nullptr, nullptr, nullptr, nullptr, 0

    // q-MLP: [1024,12544] -> relu -> [1024,1024]
    gemm_mma<true ><<<dim3(8, 8), 256, SMEM_GEMM>>>(
        xh, xl, qW1h, qW1l, 12544, NB8, qb1, nullptr, nullptr, nullptr, q1h, q1l, 1024);
    gemm_mma<false><<<dim3(8, 8), 256, SMEM_GEMM>>>(
        q1h, q1l, qW2h, qW2l, 1024, NB8, qb2, nullptr, nullptr, q, nullptr, nullptr, 1024);

    // i-MLP on ref_x: [4096,12544] -> relu -> [4096,1024]
    gemm_mma<true ><<<dim3(8, 32), 256, SMEM_GEMM>>>(
        rxh, rxl, iW1h, iW1l, 12544, NB8, ib1, nullptr, nullptr, nullptr, r1h, r1l, 1024);
    gemm_mma<false><<<dim3(8, 32), 256, SMEM_GEMM>>>(
        r1h, r1l, iW2h, iW2l, 1024, NB8, ib2, nullptr, nullptr, nullptr, rh, rl, 1024);

    // xp = r @ Wih1^T + (bih1 + bhh1)   [4096, 4096]
    gemm_mma<false><<<dim3(32, 32), 256, SMEM_GEMM>>>(
        rh, rl, Wih1h, Wih1l, 1024, NB8, bih1, bhh1, nullptr, xp, nullptr, nullptr, 4096);

    // zero LSTM state
    zero_k<<<2048, 256>>>(h1h, h1l, h2h, h2l, c1, c2);

    for (int t = 0; t < 8; ++t) {
        // layer 1: gates = xp[t] + h1 @ Whh1^T
        gemm_mma<false><<<dim3(32, 4), 256, SMEM_GEMM>>>(
            h1h, h1l, Whh1h, Whh1l, 1024, NB8,
            nullptr, nullptr, xp + (size_t)t * 512 * 4096, gates, nullptr, nullptr, 4096);
        lstm_cell_k<<<2048, 256>>>(gates, c1, nullptr, h1h, h1l);

        // layer 2: gates = h1 @ Wih2^T + h2 @ Whh2^T + bih2 + bhh2
        gemm_mma<false><<<dim3(32, 4), 256, SMEM_GEMM>>>(
            h1h, h1l, Wih2h, Wih2l, 1024,
            h2h, h2l, Whh2h, Whh2l, 1024,
            bih2, bhh2, nullptr, gates, nullptr, nullptr, 4096);
        lstm_cell_k<<<2048, 256>>>(gates, c2, h2f, h2h, h2l);
    }
#undef NB8

    final_k<<<32, 256>>>(q, h2f, out);
}

// round 5
// speedup vs baseline: 4.5982x; 1.0125x over previous
#include <cuda_runtime.h>
#include <cuda_bf16.h>

typedef unsigned long long u64;
typedef unsigned int u32;
typedef __nv_bfloat16 bf16;

// ================= scratch (device globals; no allocation) =================
__device__ bf16 g_x_h [1024u*12544], g_x_l [1024u*12544];
__device__ bf16 g_rx_h[4096u*12544], g_rx_l[4096u*12544];
__device__ bf16 g_qW1_h[1024u*12544], g_qW1_l[1024u*12544];
__device__ bf16 g_iW1_h[1024u*12544], g_iW1_l[1024u*12544];
__device__ bf16 g_qW2_h[1024u*1024], g_qW2_l[1024u*1024];
__device__ bf16 g_iW2_h[1024u*1024], g_iW2_l[1024u*1024];
// permuted (gate-interleaved) LSTM weights
__device__ bf16 g_Wih1_h[4096u*1024], g_Wih1_l[4096u*1024];
__device__ bf16 g_Whh1_h[4096u*1024], g_Whh1_l[4096u*1024];
__device__ bf16 g_Wih2_h[4096u*1024], g_Wih2_l[4096u*1024];
__device__ bf16 g_Whh2_h[4096u*1024], g_Whh2_l[4096u*1024];
__device__ float g_bs1[4096], g_bs2[4096];          // permuted bias sums
__device__ bf16 g_q1_h[1024u*1024], g_q1_l[1024u*1024];
__device__ bf16 g_r1_h[4096u*1024], g_r1_l[4096u*1024];
__device__ bf16 g_r_h [4096u*1024], g_r_l [4096u*1024];
__device__ bf16 g_h1_h[2][512u*1024], g_h1_l[2][512u*1024];   // double-buffered
__device__ bf16 g_h2_h[512u*1024], g_h2_l[512u*1024];
__device__ float g_q  [1024u*1024];
__device__ float g_xp [4096ull*4096];
__device__ float g_gates[512u*4096];
__device__ float g_c1[512u*1024], g_c2[512u*1024], g_h2f[512u*1024];

// ================= PTX helpers (baseline sm_80+ PTX only) =================
__device__ __forceinline__ u32 smem_u32(const void* p) {
    u32 a;
    asm("{ .reg .u64 t; cvta.to.shared.u64 t, %1; cvt.u32.u64 %0, t; }" : "=r"(a) : "l"(p));
    return a;
}
#define SW128(o) ((o) ^ (((o) >> 3) & 0x70))

__device__ __forceinline__ void cp16(u32 dst, const void* src) {
    asm volatile("cp.async.cg.shared.global [%0], [%1], 16;" :: "r"(dst), "l"(src));
}
#define CP_COMMIT()  asm volatile("cp.async.commit_group;" ::: "memory")
#define CP_WAIT(n)   asm volatile("cp.async.wait_group %0;" :: "n"(n) : "memory")

__device__ __forceinline__ void ldm_x4(u32& r0, u32& r1, u32& r2, u32& r3, u32 addr) {
    asm volatile("ldmatrix.sync.aligned.m8n8.x4.shared.b16 {%0,%1,%2,%3}, [%4];"
                 : "=r"(r0), "=r"(r1), "=r"(r2), "=r"(r3) : "r"(addr));
}
__device__ __forceinline__ void mma_bf16(float* d, const u32* a, const u32* b) {
    asm volatile("mma.sync.aligned.m16n8k16.row.col.f32.bf16.bf16.f32 "
                 "{%0,%1,%2,%3}, {%4,%5,%6,%7}, {%8,%9}, {%0,%1,%2,%3};"
                 : "+f"(d[0]), "+f"(d[1]), "+f"(d[2]), "+f"(d[3])
                 : "r"(a[0]), "r"(a[1]), "r"(a[2]), "r"(a[3]), "r"(b[0]), "r"(b[1]));
}

__device__ __forceinline__ float sigf(float x) {
    return __fdividef(1.0f, 1.0f + __expf(-x));
}
__device__ __forceinline__ float tanhfa(float x) {
    return __fdividef(2.0f, 1.0f + __expf(-2.0f * x)) - 1.0f;
}

// ================= shared GEMM machinery =================
// Stage layout: [Ah 16K][Al 16K][Bh 16K][Bl 16K] = 64 KB; 3 stages.
__device__ __forceinline__ void load_stage(
    u32 base,
    const bf16* __restrict__ Ah, const bf16* __restrict__ Al,
    const bf16* __restrict__ Bh, const bf16* __restrict__ Bl,
    int K, int m0, int n0, int k0, int tid)
{
#pragma unroll
    for (int i = 0; i < 4; ++i) {
        int u = tid + i * 256;
        int row = u >> 3, cu = u & 7;
        u32 so = SW128((u32)(row * 128 + cu * 16));
        size_t ao = (size_t)(m0 + row) * K + k0 + cu * 8;
        size_t bo = (size_t)(n0 + row) * K + k0 + cu * 8;
        cp16(base + so,         Ah + ao);
        cp16(base + 16384 + so, Al + ao);
        cp16(base + 32768 + so, Bh + bo);
        cp16(base + 49152 + so, Bl + bo);
    }
    CP_COMMIT();
}

__device__ __forceinline__ void compute_chunk(
    float (&acc)[4][4][4], u32 base, int lane, int wm, int wn)
{
    const int lrow = lane & 15;
    const u32 klane = (u32)((lane >> 4) * 16);
#pragma unroll
    for (int ks = 0; ks < 4; ++ks) {
        const u32 koff = ks * 32 + klane;
        u32 ah[4][4], al[4][4], bh[4][2], bl[4][2];
#pragma unroll
        for (int mt = 0; mt < 4; ++mt) {
            u32 so = SW128((u32)((wm + mt * 16 + lrow) * 128 + koff));
            ldm_x4(ah[mt][0], ah[mt][1], ah[mt][2], ah[mt][3], base + so);
            ldm_x4(al[mt][0], al[mt][1], al[mt][2], al[mt][3], base + 16384 + so);
        }
#pragma unroll
        for (int bt = 0; bt < 2; ++bt) {
            u32 so = SW128((u32)((wn + bt * 16 + lrow) * 128 + koff));
            u32 r0, r1, r2, r3;
            ldm_x4(r0, r1, r2, r3, base + 32768 + so);
            bh[bt * 2][0] = r0; bh[bt * 2][1] = r2;
            bh[bt * 2 + 1][0] = r1; bh[bt * 2 + 1][1] = r3;
            ldm_x4(r0, r1, r2, r3, base + 49152 + so);
            bl[bt * 2][0] = r0; bl[bt * 2][1] = r2;
            bl[bt * 2 + 1][0] = r1; bl[bt * 2 + 1][1] = r3;
        }
#pragma unroll
        for (int mt = 0; mt < 4; ++mt)
#pragma unroll
            for (int nt = 0; nt < 4; ++nt) {
                mma_bf16(acc[mt][nt], ah[mt], bh[nt]);   // hi*hi
                mma_bf16(acc[mt][nt], ah[mt], bl[nt]);   // hi*lo
                mma_bf16(acc[mt][nt], al[mt], bh[nt]);   // lo*hi
            }
    }
}

// 3-stage pipeline, one __syncthreads per chunk.
__device__ __forceinline__ void mainloop(
    float (&acc)[4][4][4],
    const bf16* __restrict__ Ah, const bf16* __restrict__ Al,
    const bf16* __restrict__ Bh, const bf16* __restrict__ Bl,
    int K, int m0, int n0, u32 smu, int tid, int lane, int wm, int wn)
{
#pragma unroll
    for (int i = 0; i < 4; ++i)
#pragma unroll
        for (int j = 0; j < 4; ++j)
#pragma unroll
            for (int k2 = 0; k2 < 4; ++k2) acc[i][j][k2] = 0.f;

    const int nch = K / 64;
    load_stage(smu,         Ah, Al, Bh, Bl, K, m0, n0, 0,  tid);
    load_stage(smu + 65536, Ah, Al, Bh, Bl, K, m0, n0, 64, tid);

    int sl_next = 2;   // slot receiving chunk c+2
    int sl_cur  = 0;   // slot holding chunk c
    for (int c = 0; c < nch; ++c) {
        CP_WAIT(1);
        __syncthreads();
        if (c + 2 < nch)
            load_stage(smu + sl_next * 65536, Ah, Al, Bh, Bl, K, m0, n0, (c + 2) * 64, tid);
        else
            CP_COMMIT();
        compute_chunk(acc, smu + sl_cur * 65536, lane, wm, wn);
        sl_next = (sl_next == 2) ? 0 : sl_next + 1;
        sl_cur  = (sl_cur  == 2) ? 0 : sl_cur  + 1;
    }
}

// ---- standard epilogue: bias + Cadd + relu, fp32 and/or bf16 hi/lo out ----
__device__ __forceinline__ void epi_std(
    float (&acc)[4][4][4], int m0, int n0, int lane, int wm, int wn, int N,
    const float* __restrict__ bias, const float* __restrict__ Cadd,
    float* __restrict__ Cf, bf16* __restrict__ Chi, bf16* __restrict__ Clo,
    bool relu)
{
    const int r = lane >> 2, cp = (lane & 3) * 2;
#pragma unroll
    for (int mt = 0; mt < 4; ++mt)
#pragma unroll
        for (int nt = 0; nt < 4; ++nt)
#pragma unroll
            for (int half = 0; half < 2; ++half) {
                const int m = m0 + wm + mt * 16 + r + half * 8;
                const int n = n0 + wn + nt * 8 + cp;
                float v0 = acc[mt][nt][half * 2];
                float v1 = acc[mt][nt][half * 2 + 1];
                if (bias) { v0 += bias[n]; v1 += bias[n + 1]; }
                if (Cadd) { const float* p = Cadd + (size_t)m * N + n;
                            v0 += p[0]; v1 += p[1]; }
                if (relu) { v0 = fmaxf(v0, 0.f); v1 = fmaxf(v1, 0.f); }
                if (Cf) *(float2*)(Cf + (size_t)m * N + n) = make_float2(v0, v1);
                if (Chi) {
                    bf16 h0 = __float2bfloat16(v0), h1 = __float2bfloat16(v1);
                    bf16 l0 = __float2bfloat16(v0 - __bfloat162float(h0));
                    bf16 l1 = __float2bfloat16(v1 - __bfloat162float(h1));
                    *(__nv_bfloat162*)(Chi + (size_t)m * N + n) = __nv_bfloat162(h0, h1);
                    *(__nv_bfloat162*)(Clo + (size_t)m * N + n) = __nv_bfloat162(l0, l1);
                }
            }
}

// ---- LSTM-cell epilogue: gate cols permuted (4j+g), shuffle-pair exchange ----
__device__ __forceinline__ void epi_cell(
    float (&acc)[4][4][4], int m0, int n0, int lane, int wm, int wn,
    const float* __restrict__ bias, const float* __restrict__ Cadd,
    float* __restrict__ cbuf, bf16* __restrict__ hh, bf16* __restrict__ hl,
    float* __restrict__ hf, bool zc)
{
    const int r = lane >> 2, cp = (lane & 3) * 2;
#pragma unroll
    for (int mt = 0; mt < 4; ++mt)
#pragma unroll
        for (int nt = 0; nt < 4; ++nt)
#pragma unroll
            for (int half = 0; half < 2; ++half) {
                const int m = m0 + wm + mt * 16 + r + half * 8;     // row in [0,512)
                const int n = n0 + wn + nt * 8 + cp;                // gate col [0,4096)
                float v0 = acc[mt][nt][half * 2];
                float v1 = acc[mt][nt][half * 2 + 1];
                if (bias) { v0 += bias[n]; v1 += bias[n + 1]; }
                if (Cadd) { const float* p = Cadd + (size_t)m * 4096 + n;
                            v0 += p[0]; v1 += p[1]; }
                // even lane holds (i,f); odd partner (lane^1) holds (g,o)
                float w0 = __shfl_xor_sync(0xFFFFFFFFu, v0, 1);
                float w1 = __shfl_xor_sync(0xFFFFFFFFu, v1, 1);
                if ((lane & 1) == 0) {
                    const int hc = n >> 2;
                    const size_t hidx = (size_t)m * 1024 + hc;
                    float cprev = zc ? 0.f : cbuf[hidx];
                    float cc = sigf(v1) * cprev + sigf(v0) * tanhfa(w0);
                    cbuf[hidx] = cc;
                    float h = sigf(w1) * tanhfa(cc);
                    bf16 hb = __float2bfloat16(h);
                    hh[hidx] = hb;
                    hl[hidx] = __float2bfloat16(h - __bfloat162float(hb));
                    if (hf) hf[hidx] = h;
                }
            }
}

// ================= GEMM kernels =================
static const int SMEM_GEMM = 3 * 65536;   // 192 KB

// dual-region MLP layer: region0 (q, nby0 row-blocks) + region1 (i). N = 1024.
template <bool RELU>
__global__ void __launch_bounds__(256, 1) mlp_dual(
    const bf16* __restrict__ A0h, const bf16* __restrict__ A0l,
    const bf16* __restrict__ B0h, const bf16* __restrict__ B0l,
    const float* __restrict__ b0, float* __restrict__ C0f,
    bf16* __restrict__ C0h, bf16* __restrict__ C0l, int nby0,
    const bf16* __restrict__ A1h, const bf16* __restrict__ A1l,
    const bf16* __restrict__ B1h, const bf16* __restrict__ B1l,
    const float* __restrict__ b1, float* __restrict__ C1f,
    bf16* __restrict__ C1h, bf16* __restrict__ C1l,
    int K)
{
    extern __shared__ char sm[];
    const int tid = threadIdx.x, wid = tid >> 5, lane = tid & 31;
    const int wm = (wid >> 2) * 64, wn = (wid & 3) * 32;
    const bool r0 = (int)blockIdx.y < nby0;
    const int m0 = (r0 ? blockIdx.y : blockIdx.y - nby0) * 128;
    const int n0 = blockIdx.x * 128;
    const u32 smu = smem_u32(sm);

    float acc[4][4][4];
    mainloop(acc, r0 ? A0h : A1h, r0 ? A0l : A1l, r0 ? B0h : B1h, r0 ? B0l : B1l,
             K, m0, n0, smu, tid, lane, wm, wn);
    epi_std(acc, m0, n0, lane, wm, wn, 1024,
            r0 ? b0 : b1, nullptr,
            r0 ? C0f : C1f, r0 ? C0h : C1h, r0 ? C0l : C1l, RELU);
}

// single GEMM: xp = r @ Wih1'^T + bs1   (M=4096, N=4096, K=1024)
__global__ void __launch_bounds__(256, 1) gemm_xp(
    const bf16* __restrict__ Ah, const bf16* __restrict__ Al,
    const bf16* __restrict__ Bh, const bf16* __restrict__ Bl,
    const float* __restrict__ bias, float* __restrict__ Cf)
{
    extern __shared__ char sm[];
    const int tid = threadIdx.x, wid = tid >> 5, lane = tid & 31;
    const int wm = (wid >> 2) * 64, wn = (wid & 3) * 32;
    const int m0 = blockIdx.y * 128, n0 = blockIdx.x * 128;
    const u32 smu = smem_u32(sm);

    float acc[4][4][4];
    mainloop(acc, Ah, Al, Bh, Bl, 1024, m0, n0, smu, tid, lane, wm, wn);
    epi_std(acc, m0, n0, lane, wm, wn, 4096, bias, nullptr, Cf, nullptr, nullptr, false);
}

// LSTM step A: grid (32, 8).
//   by<4:  G1 = h1_prev @ Whh1' + xp[t]  -> cell -> h1_new, c1
//   by>=4: G2a = h2 @ Whh2' + bs2        -> gates2 (fp32)
__global__ void __launch_bounds__(256, 1) lstm_stepA(
    const bf16* __restrict__ h1h, const bf16* __restrict__ h1l,
    const bf16* __restrict__ W1h, const bf16* __restrict__ W1l,
    const float* __restrict__ xpt, float* __restrict__ c1,
    bf16* __restrict__ oh1h, bf16* __restrict__ oh1l,
    const bf16* __restrict__ h2h, const bf16* __restrict__ h2l,
    const bf16* __restrict__ W2h, const bf16* __restrict__ W2l,
    const float* __restrict__ bs2, float* __restrict__ gates2)
{
    extern __shared__ char sm[];
    const int tid = threadIdx.x, wid = tid >> 5, lane = tid & 31;
    const int wm = (wid >> 2) * 64, wn = (wid & 3) * 32;
    const bool g1 = (int)blockIdx.y < 4;
    const int m0 = (g1 ? blockIdx.y : blockIdx.y - 4) * 128;
    const int n0 = blockIdx.x * 128;
    const u32 smu = smem_u32(sm);

    float acc[4][4][4];
    mainloop(acc, g1 ? h1h : h2h, g1 ? h1l : h2l, g1 ? W1h : W2h, g1 ? W1l : W2l,
             1024, m0, n0, smu, tid, lane, wm, wn);
    if (g1)
        epi_cell(acc, m0, n0, lane, wm, wn, nullptr, xpt, c1, oh1h, oh1l, nullptr, false);
    else
        epi_std(acc, m0, n0, lane, wm, wn, 4096, bs2, nullptr, gates2, nullptr, nullptr, false);
}

// LSTM step B: grid (32, 4). gates = h1_new @ Wih2' (+ gates2 | + bs2) -> cell -> h2, c2
template <bool ZC>
__global__ void __launch_bounds__(256, 1) lstm_stepB(
    const bf16* __restrict__ h1h, const bf16* __restrict__ h1l,
    const bf16* __restrict__ Wh, const bf16* __restrict__ Wl,
    const float* __restrict__ Cadd, const float* __restrict__ bias,
    float* __restrict__ c2, bf16* __restrict__ oh2h, bf16* __restrict__ oh2l,
    float* __restrict__ h2f)
{
    extern __shared__ char sm[];
    const int tid = threadIdx.x, wid = tid >> 5, lane = tid & 31;
    const int wm = (wid >> 2) * 64, wn = (wid & 3) * 32;
    const int m0 = blockIdx.y * 128, n0 = blockIdx.x * 128;
    const u32 smu = smem_u32(sm);

    float acc[4][4][4];
    mainloop(acc, h1h, h1l, Wh, Wl, 1024, m0, n0, smu, tid, lane, wm, wn);
    epi_cell(acc, m0, n0, lane, wm, wn, bias, Cadd, c2, oh2h, oh2l, h2f, ZC);
}

// ================= elementwise kernels =================
__global__ void split8_k(const float* __restrict__ src, bf16* __restrict__ hi,
                         bf16* __restrict__ lo)
{
    size_t i = ((size_t)blockIdx.x * blockDim.x + threadIdx.x) * 8;
#pragma unroll
    for (int b = 0; b < 2; ++b) {
        float4 v = *(const float4*)(src + i + b * 4);
        float vv[4] = {v.x, v.y, v.z, v.w};
        unsigned short hh[4], ll[4];
#pragma unroll
        for (int j = 0; j < 4; ++j) {
            bf16 h = __float2bfloat16(vv[j]);
            bf16 l = __float2bfloat16(vv[j] - __bfloat162float(h));
            hh[j] = __bfloat16_as_ushort(h);
            ll[j] = __bfloat16_as_ushort(l);
        }
        *(ushort4*)(hi + i + b * 4) = make_ushort4(hh[0], hh[1], hh[2], hh[3]);
        *(ushort4*)(lo + i + b * 4) = make_ushort4(ll[0], ll[1], ll[2], ll[3]);
    }
}

// split + gate-permute LSTM weight [4096,1024]: out row 4*(r&1023)+(r>>10)
__global__ void splitperm_k(const float* __restrict__ W, bf16* __restrict__ hi,
                            bf16* __restrict__ lo)
{
    size_t i = ((size_t)blockIdx.x * blockDim.x + threadIdx.x) * 8;
    int r = (int)(i >> 10), col = (int)(i & 1023);
    int ro = ((r & 1023) << 2) | (r >> 10);
    size_t o = (size_t)ro * 1024 + col;
#pragma unroll
    for (int b = 0; b < 2; ++b) {
        float4 v = *(const float4*)(W + i + b * 4);
        float vv[4] = {v.x, v.y, v.z, v.w};
        unsigned short hh[4], ll[4];
#pragma unroll
        for (int j = 0; j < 4; ++j) {
            bf16 h = __float2bfloat16(vv[j]);
            bf16 l = __float2bfloat16(vv[j] - __bfloat162float(h));
            hh[j] = __bfloat16_as_ushort(h);
            ll[j] = __bfloat16_as_ushort(l);
        }
        *(ushort4*)(hi + o + b * 4) = make_ushort4(hh[0], hh[1], hh[2], hh[3]);
        *(ushort4*)(lo + o + b * 4) = make_ushort4(ll[0], ll[1], ll[2], ll[3]);
    }
}

__global__ void biasperm_k(const float* __restrict__ bih1, const float* __restrict__ bhh1,
                           const float* __restrict__ bih2, const float* __restrict__ bhh2,
                           float* __restrict__ bs1, float* __restrict__ bs2)
{
    int j = blockIdx.x * blockDim.x + threadIdx.x;   // < 4096
    int o = (j >> 2) + ((j & 3) << 10);
    bs1[j] = bih1[o] + bhh1[o];
    bs2[j] = bih2[o] + bhh2[o];
}

// t=0 layer-1 cell directly from xp[0] (h1=c1=0 prior)
__global__ void cell1_t0_k(const float* __restrict__ xp0, float* __restrict__ c1,
                           bf16* __restrict__ hh, bf16* __restrict__ hl)
{
    int idx = blockIdx.x * blockDim.x + threadIdx.x;   // < 512*1024
    int m = idx >> 10, hc = idx & 1023;
    float4 g = *(const float4*)(xp0 + (size_t)m * 4096 + hc * 4);
    float cc = sigf(g.x) * tanhfa(g.z);
    c1[idx] = cc;
    float h = sigf(g.w) * tanhfa(cc);
    bf16 hb = __float2bfloat16(h);
    hh[idx] = hb;
    hl[idx] = __float2bfloat16(h - __bfloat162float(hb));
}

// ================= final einsum =================
__global__ void final_k(const float* __restrict__ q, const float* __restrict__ h,
                        float* __restrict__ out)
{
    __shared__ float qs[32][33];
    __shared__ float hs[64][33];
    const int b  = blockIdx.x >> 2;
    const int rt = blockIdx.x & 3;
    const int tid = threadIdx.x;
    const int r  = tid & 31;
    const int cg = tid >> 5;

    float acc[8] = {0.f, 0.f, 0.f, 0.f, 0.f, 0.f, 0.f, 0.f};
    for (int k0 = 0; k0 < 1024; k0 += 32) {
        __syncthreads();
        for (int i = tid; i < 32 * 32; i += 256) {
            int rr = i >> 5, kk = i & 31;
            qs[rr][kk] = q[(size_t)(b * 128 + rt * 32 + rr) * 1024 + k0 + kk];
        }
        for (int i = tid; i < 64 * 32; i += 256) {
            int rr = i >> 5, kk = i & 31;
            hs[rr][kk] = h[(size_t)(b * 64 + rr) * 1024 + k0 + kk];
        }
        __syncthreads();
#pragma unroll
        for (int kk = 0; kk < 32; ++kk) {
            float qa = qs[r][kk];
#pragma unroll
            for (int j = 0; j < 8; ++j) acc[j] += qa * hs[cg * 8 + j][kk];
        }
    }
    const int row = rt * 32 + r;
    float* op = out + ((size_t)b * 128 + row) * 65;
#pragma unroll
    for (int j = 0; j < 8; ++j) op[1 + cg * 8 + j] = acc[j];
    if (cg == 0) op[0] = 0.f;
}

// ================= host =================
extern "C" void kernel_launch(void* const* d_in, const int* in_sizes, int n_in,
                              void* d_out, int out_size)
{
    const float* x    = (const float*)d_in[0];
    const float* refx = (const float*)d_in[1];
    const float* qW1  = (const float*)d_in[2];
    const float* qb1  = (const float*)d_in[3];
    const float* qW2  = (const float*)d_in[4];
    const float* qb2  = (const float*)d_in[5];
    const float* iW1  = (const float*)d_in[6];
    const float* ib1  = (const float*)d_in[7];
    const float* iW2  = (const float*)d_in[8];
    const float* ib2  = (const float*)d_in[9];
    const float* Wih1 = (const float*)d_in[10];
    const float* Whh1 = (const float*)d_in[11];
    const float* bih1 = (const float*)d_in[12];
    const float* bhh1 = (const float*)d_in[13];
    const float* Wih2 = (const float*)d_in[14];
    const float* Whh2 = (const float*)d_in[15];
    const float* bih2 = (const float*)d_in[16];
    const float* bhh2 = (const float*)d_in[17];
    float* out = (float*)d_out;

    cudaFuncSetAttribute(mlp_dual<true >, cudaFuncAttributeMaxDynamicSharedMemorySize, SMEM_GEMM);
    cudaFuncSetAttribute(mlp_dual<false>, cudaFuncAttributeMaxDynamicSharedMemorySize, SMEM_GEMM);
    cudaFuncSetAttribute(gemm_xp,         cudaFuncAttributeMaxDynamicSharedMemorySize, SMEM_GEMM);
    cudaFuncSetAttribute(lstm_stepA,      cudaFuncAttributeMaxDynamicSharedMemorySize, SMEM_GEMM);
    cudaFuncSetAttribute(lstm_stepB<true >, cudaFuncAttributeMaxDynamicSharedMemorySize, SMEM_GEMM);
    cudaFuncSetAttribute(lstm_stepB<false>, cudaFuncAttributeMaxDynamicSharedMemorySize, SMEM_GEMM);

#define SYM(v, s) cudaGetSymbolAddress((void**)&v, s)
    bf16 *xh, *xl, *rxh, *rxl, *qW1h, *qW1l, *iW1h, *iW1l, *qW2h, *qW2l, *iW2h, *iW2l;
    bf16 *Wih1h, *Wih1l, *Whh1h, *Whh1l, *Wih2h, *Wih2l, *Whh2h, *Whh2l;
    bf16 *q1h, *q1l, *r1h, *r1l, *rh, *rl, *h1hb, *h1lb, *h2h, *h2l;
    float *bs1, *bs2, *q, *xp, *gates, *c1, *c2, *h2f;
    SYM(xh, g_x_h);   SYM(xl, g_x_l);   SYM(rxh, g_rx_h);   SYM(rxl, g_rx_l);
    SYM(qW1h, g_qW1_h); SYM(qW1l, g_qW1_l); SYM(iW1h, g_iW1_h); SYM(iW1l, g_iW1_l);
    SYM(qW2h, g_qW2_h); SYM(qW2l, g_qW2_l); SYM(iW2h, g_iW2_h); SYM(iW2l, g_iW2_l);
    SYM(Wih1h, g_Wih1_h); SYM(Wih1l, g_Wih1_l); SYM(Whh1h, g_Whh1_h); SYM(Whh1l, g_Whh1_l);
    SYM(Wih2h, g_Wih2_h); SYM(Wih2l, g_Wih2_l); SYM(Whh2h, g_Whh2_h); SYM(Whh2l, g_Whh2_l);
    SYM(q1h, g_q1_h); SYM(q1l, g_q1_l); SYM(r1h, g_r1_h); SYM(r1l, g_r1_l);
    SYM(rh, g_r_h);   SYM(rl, g_r_l);
    SYM(h1hb, g_h1_h); SYM(h1lb, g_h1_l); SYM(h2h, g_h2_h); SYM(h2l, g_h2_l);
    SYM(bs1, g_bs1); SYM(bs2, g_bs2);
    SYM(q, g_q); SYM(xp, g_xp); SYM(gates, g_gates);
    SYM(c1, g_c1); SYM(c2, g_c2); SYM(h2f, g_h2f);
#undef SYM
    const size_t HB = 512u * 1024;   // h1 buffer stride
    bf16* h1h[2] = {h1hb, h1hb + HB};
    bf16* h1l[2] = {h1lb, h1lb + HB};

    // ---- splits (fp32 -> bf16 hi/lo; LSTM weights also gate-permuted) ----
    split8_k<<<6272,  256>>>(x,    xh,   xl);
    split8_k<<<25088, 256>>>(refx, rxh,  rxl);
    split8_k<<<6272,  256>>>(qW1,  qW1h, qW1l);
    split8_k<<<6272,  256>>>(iW1,  iW1h, iW1l);
    split8_k<<<512,   256>>>(qW2,  qW2h, qW2l);
    split8_k<<<512,   256>>>(iW2,  iW2h, iW2l);
    splitperm_k<<<2048, 256>>>(Wih1, Wih1h, Wih1l);
    splitperm_k<<<2048, 256>>>(Whh1, Whh1h, Whh1l);
    splitperm_k<<<2048, 256>>>(Wih2, Wih2h, Wih2l);
    splitperm_k<<<2048, 256>>>(Whh2, Whh2h, Whh2l);
    biasperm_k<<<16, 256>>>(bih1, bhh1, bih2, bhh2, bs1, bs2);

    // ---- MLPs (q-region + i-region fused per layer) ----
    mlp_dual<true ><<<dim3(8, 40), 256, SMEM_GEMM>>>(
        xh, xl, qW1h, qW1l, qb1, nullptr, q1h, q1l, 8,
        rxh, rxl, iW1h, iW1l, ib1, nullptr, r1h, r1l, 12544);
    mlp_dual<false><<<dim3(8, 40), 256, SMEM_GEMM>>>(
        q1h, q1l, qW2h, qW2l, qb2, q, nullptr, nullptr, 8,
        r1h, r1l, iW2h, iW2l, ib2, nullptr, rh, rl, 1024);

    // ---- xp = r @ Wih1'^T + bs1  (permuted gate cols) ----
    gemm_xp<<<dim3(32, 32), 256, SMEM_GEMM>>>(rh, rl, Wih1h, Wih1l, bs1, xp);

    // ---- LSTM: t=0 special-cased, then 7 fused steps ----
    cell1_t0_k<<<2048, 256>>>(xp, c1, h1h[0], h1l[0]);
    lstm_stepB<true ><<<dim3(32, 4), 256, SMEM_GEMM>>>(
        h1h[0], h1l[0], Wih2h, Wih2l, nullptr, bs2, c2, h2h, h2l, h2f);

    for (int t = 1; t < 8; ++t) {
        const int pr = (t - 1) & 1, pw = t & 1;
        lstm_stepA<<<dim3(32, 8), 256, SMEM_GEMM>>>(
            h1h[pr], h1l[pr], Whh1h, Whh1l, xp + (size_t)t * 512 * 4096,
            c1, h1h[pw], h1l[pw],
            h2h, h2l, Whh2h, Whh2l, bs2, gates);
        lstm_stepB<false><<<dim3(32, 4), 256, SMEM_GEMM>>>(
            h1h[pw], h1l[pw], Wih2h, Wih2l, gates, nullptr, c2, h2h, h2l, h2f);
    }

    // ---- out[b,q,k]: zero col + q @ h2^T per batch ----
    final_k<<<32, 256>>>(q, h2f, out);
}